// round 4
// baseline (speedup 1.0000x reference)
#include <cuda_runtime.h>
#include <math.h>
#include <stdint.h>

// ---------------------------------------------------------------------------
// NormalVariationBoundaryLoss
//   loss = sum_p( ce_p * w_p * vm_p ) / max(sum_p vm_p, 1)
//   w_p  = 1 + 3 * clip((diff_p - dmin)/(dmax - dmin + 1e-6), 0, 1)
//   diff = 1 - clip(cos(normalize(n_p), normalize(voxel_sum_n)), -1, 1)
//   Voxel grouping == group by (x,y,z,batch); reference int64 hash is
//   injective over these ranges -> 30-bit packed key + open-addressing table.
//   L2 strategy: all streaming inputs use __ldcs (evict-first) so the 67MB
//   interleaved table {key,sx,sy,sz} stays L2-resident across all passes.
// ---------------------------------------------------------------------------

#define TABLE_BITS 22
#define TSIZE (1u << TABLE_BITS)
#define NMAX 2097152

// zero-initialized device scratch (allocation-free per harness rules)
__device__ uint4        g_table[TSIZE];   // {key+1 (0=empty), sx, sy, sz}
__device__ int          g_slot[NMAX];
__device__ float        g_diff[NMAX];
__device__ float        g_ce[NMAX];
__device__ unsigned int g_dmin_bits;
__device__ unsigned int g_dmax_bits;
__device__ double       g_loss;
__device__ double       g_vm;
__device__ unsigned int g_odd_or;         // 0 => int inputs are int64

// ---------------------------------------------------------------------------
// Fused init + dtype detect. int64 little-endian (values < 2^31) => all odd
// 32-bit words zero. Reads first n32 words: in-bounds for BOTH dtypes.
__global__ void detect_init_kernel(const unsigned int* __restrict__ w, int n32) {
    if (blockIdx.x == 0 && threadIdx.x == 0) {
        g_dmin_bits = 0x7f800000u;  // +inf
        g_dmax_bits = 0u;
        g_loss = 0.0;
        g_vm   = 0.0;
    }
    unsigned int acc = 0u;
    int stride = gridDim.x * blockDim.x;
    for (int i = blockIdx.x * blockDim.x + threadIdx.x; 2 * i + 1 < n32; i += stride)
        acc |= __ldcs(w + 2 * i + 1);
#pragma unroll
    for (int o = 16; o; o >>= 1) acc |= __shfl_xor_sync(0xffffffffu, acc, o);
    if ((threadIdx.x & 31) == 0 && acc) atomicOr(&g_odd_or, acc);
}

__device__ __forceinline__ long long ld_idx_cs(const void* p, long long i, bool is64) {
    return is64 ? __ldcs((const long long*)p + i)
                : (long long)__ldcs((const int*)p + i);
}

// ---------------------------------------------------------------------------
// Per-point: insert voxel key into hash table, accumulate normal sums.
__global__ void hash_kernel(const void* __restrict__ gc,
                            const void* __restrict__ batch,
                            const void* __restrict__ target,
                            const float* __restrict__ normal,
                            int n) {
    const bool is64 = (g_odd_or == 0u);
    int p = blockIdx.x * blockDim.x + threadIdx.x;
    if (p >= n) return;

    long long t = ld_idx_cs(target, p, is64);
    if (t == -1LL) { g_slot[p] = -1; return; }

    unsigned int x = (unsigned int)ld_idx_cs(gc, 3LL * p + 0, is64);
    unsigned int y = (unsigned int)ld_idx_cs(gc, 3LL * p + 1, is64);
    unsigned int z = (unsigned int)ld_idx_cs(gc, 3LL * p + 2, is64);
    unsigned int b = (unsigned int)ld_idx_cs(batch, p, is64);
    // 9 bits per coord, 3 bits batch -> injective for x,y,z<512, b<8
    unsigned int key = ((b << 27) | (x << 18) | (y << 9) | z) + 1u;

    unsigned int* tbl = (unsigned int*)g_table;
    unsigned int h = (key * 2654435761u) >> (32 - TABLE_BITS);
    while (true) {
        unsigned int prev = atomicCAS(&tbl[4u * h], 0u, key);
        if (prev == 0u || prev == key) break;
        h = (h + 1u) & (TSIZE - 1u);
    }
    g_slot[p] = (int)h;

    float nx = __ldcs(normal + 3 * p + 0);
    float ny = __ldcs(normal + 3 * p + 1);
    float nz = __ldcs(normal + 3 * p + 2);
    float* fs = (float*)g_table + 4u * h;
    atomicAdd(fs + 1, nx);
    atomicAdd(fs + 2, ny);
    atomicAdd(fs + 3, nz);
}

// ---------------------------------------------------------------------------
// Fused pass: warp per point. Computes diff (table gather, should L2-hit),
// CE (coalesced evict-first 128B pred row), stores both, block-reduced
// global min/max of diff. l2_normalize(sum/cnt)==l2_normalize(sum).
__global__ void main_kernel(const float* __restrict__ pred,
                            const void* __restrict__ target,
                            const float* __restrict__ normal,
                            int n, int C) {
    __shared__ float sh_min[8];
    __shared__ float sh_max[8];

    const bool is64 = (g_odd_or == 0u);
    int lane = threadIdx.x & 31;
    int gw   = (blockIdx.x * blockDim.x + threadIdx.x) >> 5;
    int nwrp = (gridDim.x * blockDim.x) >> 5;

    float lmin = INFINITY;
    float lmax = -INFINITY;

    for (int p = gw; p < n; p += nwrp) {
        int s = g_slot[p];  // broadcast load (all lanes same addr)
        if (s < 0) {
            if (lane == 0) { g_diff[p] = -1.f; g_ce[p] = 0.f; }
            continue;
        }
        // --- diff (all lanes compute redundantly; broadcast loads) ---
        float4 f = ((const float4*)g_table)[s];
        float nx = __ldcs(normal + 3 * p + 0);
        float ny = __ldcs(normal + 3 * p + 1);
        float nz = __ldcs(normal + 3 * p + 2);
        float sn = sqrtf(f.y * f.y + f.z * f.z + f.w * f.w);
        float nn = sqrtf(nx * nx + ny * ny + nz * nz);
        float inv = 1.f / (fmaxf(sn, 1e-6f) * fmaxf(nn, 1e-6f));
        float c = (f.y * nx + f.z * ny + f.w * nz) * inv;
        c = fminf(fmaxf(c, -1.f), 1.f);
        float d = 1.f - c;
        lmin = fminf(lmin, d);
        lmax = fmaxf(lmax, d);

        // --- cross entropy ---
        long long t = ld_idx_cs(target, p, is64);
        const float* row = pred + (size_t)p * (size_t)C;
        float ce;
        if (C == 32) {
            float x = __ldcs(row + lane);
            float m = x;
#pragma unroll
            for (int o = 16; o; o >>= 1) m = fmaxf(m, __shfl_xor_sync(0xffffffffu, m, o));
            float e = __expf(x - m);
#pragma unroll
            for (int o = 16; o; o >>= 1) e += __shfl_xor_sync(0xffffffffu, e, o);
            float xt = __shfl_sync(0xffffffffu, x, (int)t);
            ce = m + __logf(e) - xt;
        } else {
            int iters = (C + 31) >> 5;
            if (iters > 8) iters = 8;  // C <= 256
            float xs[8];
            float m  = -INFINITY;
            float xt = 0.f;
#pragma unroll
            for (int i = 0; i < 8; i++) {
                if (i >= iters) break;
                int cidx = i * 32 + lane;
                float xv = (cidx < C) ? __ldcs(row + cidx) : -INFINITY;
                xs[i] = xv;
                m = fmaxf(m, xv);
                if ((long long)cidx == t) xt = xv;
            }
#pragma unroll
            for (int o = 16; o; o >>= 1) m = fmaxf(m, __shfl_xor_sync(0xffffffffu, m, o));
            float sum = 0.f;
#pragma unroll
            for (int i = 0; i < 8; i++) {
                if (i >= iters) break;
                sum += __expf(xs[i] - m);
            }
#pragma unroll
            for (int o = 16; o; o >>= 1) sum += __shfl_xor_sync(0xffffffffu, sum, o);
#pragma unroll
            for (int o = 16; o; o >>= 1) xt  += __shfl_xor_sync(0xffffffffu, xt, o);
            ce = m + __logf(sum) - xt;
        }

        if (lane == 0) { g_diff[p] = d; g_ce[p] = ce; }
    }

    // block reduce min/max, one atomic pair per block
#pragma unroll
    for (int o = 16; o; o >>= 1) {
        lmin = fminf(lmin, __shfl_xor_sync(0xffffffffu, lmin, o));
        lmax = fmaxf(lmax, __shfl_xor_sync(0xffffffffu, lmax, o));
    }
    int wid = threadIdx.x >> 5;
    if (lane == 0) { sh_min[wid] = lmin; sh_max[wid] = lmax; }
    __syncthreads();
    if (wid == 0) {
        int nw = blockDim.x >> 5;
        lmin = (lane < nw) ? sh_min[lane] : INFINITY;
        lmax = (lane < nw) ? sh_max[lane] : -INFINITY;
#pragma unroll
        for (int o = 16; o; o >>= 1) {
            lmin = fminf(lmin, __shfl_xor_sync(0xffffffffu, lmin, o));
            lmax = fmaxf(lmax, __shfl_xor_sync(0xffffffffu, lmax, o));
        }
        if (lane == 0) {
            if (lmin <= 2.f) atomicMin(&g_dmin_bits, __float_as_uint(lmin));
            if (lmax >= 0.f) atomicMax(&g_dmax_bits, __float_as_uint(lmax));
        }
    }
}

// ---------------------------------------------------------------------------
// Cheap pass: read ce/diff (16MB), apply weight, reduce.
__global__ void finalize_kernel(int n) {
    __shared__ double sh_loss[8];
    __shared__ double sh_cnt[8];

    float dmin = __uint_as_float(g_dmin_bits);
    float dmax = __uint_as_float(g_dmax_bits);
    float invr = 1.f / (dmax - dmin + 1e-6f);

    double lsum = 0.0;
    double lcnt = 0.0;

    int stride = gridDim.x * blockDim.x;
    for (int p = blockIdx.x * blockDim.x + threadIdx.x; p < n; p += stride) {
        float d = __ldcs(&g_diff[p]);
        if (d < 0.f) continue;
        float ce = __ldcs(&g_ce[p]);
        float dn = (d - dmin) * invr;
        dn = fminf(fmaxf(dn, 0.f), 1.f);
        lsum += (double)(ce * (1.f + 3.f * dn));
        lcnt += 1.0;
    }

#pragma unroll
    for (int o = 16; o; o >>= 1) {
        lsum += __shfl_xor_sync(0xffffffffu, lsum, o);
        lcnt += __shfl_xor_sync(0xffffffffu, lcnt, o);
    }
    int wid = threadIdx.x >> 5, lane = threadIdx.x & 31;
    if (lane == 0) { sh_loss[wid] = lsum; sh_cnt[wid] = lcnt; }
    __syncthreads();
    if (wid == 0) {
        int nw = blockDim.x >> 5;
        lsum = (lane < nw) ? sh_loss[lane] : 0.0;
        lcnt = (lane < nw) ? sh_cnt[lane] : 0.0;
#pragma unroll
        for (int o = 16; o; o >>= 1) {
            lsum += __shfl_xor_sync(0xffffffffu, lsum, o);
            lcnt += __shfl_xor_sync(0xffffffffu, lcnt, o);
        }
        if (lane == 0) {
            atomicAdd(&g_loss, lsum);
            atomicAdd(&g_vm, lcnt);
        }
    }
}

// ---------------------------------------------------------------------------
__global__ void writeout_kernel(float* __restrict__ out) {
    double denom = g_vm > 1.0 ? g_vm : 1.0;
    out[0] = (float)(g_loss / denom);  // LOSS_WEIGHT = 1
}

// ---------------------------------------------------------------------------
// Streaming clear of the hash table. Plain stores: dirty lines stay in L2
// so the NEXT replay's CAS pass hits L2.
__global__ void clear_kernel() {
    uint4 z = make_uint4(0u, 0u, 0u, 0u);
    unsigned int stride = gridDim.x * blockDim.x;
    for (unsigned int i = blockIdx.x * blockDim.x + threadIdx.x; i < TSIZE; i += stride)
        g_table[i] = z;
}

// ---------------------------------------------------------------------------
extern "C" void kernel_launch(void* const* d_in, const int* in_sizes, int n_in,
                              void* d_out, int out_size) {
    const float* pred   = (const float*)d_in[0];
    const void*  target = d_in[1];
    const void*  gcoord = d_in[2];
    const float* normal = (const float*)d_in[3];
    const void*  batch  = d_in[4];
    float* out = (float*)d_out;

    int n = in_sizes[1];              // number of points
    int C = in_sizes[0] / n;          // number of classes (32)

    detect_init_kernel<<<256, 256>>>((const unsigned int*)gcoord, n * 3);

    {
        int threads = 256;
        int blocks = (n + threads - 1) / threads;
        hash_kernel<<<blocks, threads>>>(gcoord, batch, target, normal, n);
    }

    main_kernel<<<2960, 256>>>(pred, target, normal, n, C);

    finalize_kernel<<<1480, 256>>>(n);

    writeout_kernel<<<1, 1>>>(out);

    clear_kernel<<<1480, 256>>>();
}

// round 7
// speedup vs baseline: 1.2865x; 1.2865x over previous
#include <cuda_runtime.h>
#include <math.h>
#include <stdint.h>

// ---------------------------------------------------------------------------
// NormalVariationBoundaryLoss
//   Voxel grouping by (x,y,z,batch), x,y,z in [0,128), batch in [0,8):
//   24-bit key -> DIRECT-INDEXED table (no hashing, no CAS, no probing).
//   l2_normalize(sum/cnt) == l2_normalize(sum) -> only normal sums needed.
//   loss = sum(ce * w * vm) / max(sum vm, 1),
//   w = 1 + 3*clip((diff-dmin)/(dmax-dmin+1e-6),0,1),
//   diff = 1 - clip(cos(normalize(n), normalize(voxel_sum)), -1, 1)
// ---------------------------------------------------------------------------

#define KEY_SPACE (1 << 24)   // 16.7M slots
#define NMAX 2097152

// zero-initialized device scratch (allocation-free per harness rules)
__device__ float4       g_sums[KEY_SPACE];  // .x/.y/.z = normal sums (268MB)
__device__ int          g_slot[NMAX];       // 24-bit key or -1
__device__ float        g_diff[NMAX];
__device__ unsigned int g_dmin_bits;
__device__ unsigned int g_dmax_bits;
__device__ double       g_loss;
__device__ double       g_vm;
__device__ unsigned int g_odd_or;           // 0 => int inputs are int64

// ---------------------------------------------------------------------------
// Fused init + dtype detect (samples first 256K word-pairs: 1MB).
// int64 little-endian (values < 2^31) => all odd 32-bit words zero.
__global__ void detect_init_kernel(const unsigned int* __restrict__ w, int n32) {
    if (blockIdx.x == 0 && threadIdx.x == 0) {
        g_dmin_bits = 0x7f800000u;  // +inf
        g_dmax_bits = 0u;
        g_loss = 0.0;
        g_vm   = 0.0;
    }
    int limit = n32 / 2;
    if (limit > 262144) limit = 262144;
    unsigned int acc = 0u;
    int stride = gridDim.x * blockDim.x;
    for (int i = blockIdx.x * blockDim.x + threadIdx.x; i < limit; i += stride)
        acc |= __ldcs(w + 2 * i + 1);
#pragma unroll
    for (int o = 16; o; o >>= 1) acc |= __shfl_xor_sync(0xffffffffu, acc, o);
    if ((threadIdx.x & 31) == 0 && acc) atomicOr(&g_odd_or, acc);
}

__device__ __forceinline__ long long ld_idx_cs(const void* p, long long i, bool is64) {
    return is64 ? __ldcs((const long long*)p + i)
                : (long long)__ldcs((const int*)p + i);
}

// ---------------------------------------------------------------------------
// Per-point scatter: direct-indexed accumulation of normals. No CAS.
__global__ void scatter_kernel(const void* __restrict__ gc,
                               const void* __restrict__ batch,
                               const void* __restrict__ target,
                               const float* __restrict__ normal,
                               int n) {
    const bool is64 = (g_odd_or == 0u);
    int p = blockIdx.x * blockDim.x + threadIdx.x;
    if (p >= n) return;

    long long t = ld_idx_cs(target, p, is64);
    if (t == -1LL) { g_slot[p] = -1; return; }

    unsigned int x = (unsigned int)ld_idx_cs(gc, 3LL * p + 0, is64) & 127u;
    unsigned int y = (unsigned int)ld_idx_cs(gc, 3LL * p + 1, is64) & 127u;
    unsigned int z = (unsigned int)ld_idx_cs(gc, 3LL * p + 2, is64) & 127u;
    unsigned int b = (unsigned int)ld_idx_cs(batch, p, is64) & 7u;
    unsigned int key = (b << 21) | (x << 14) | (y << 7) | z;  // 24-bit, injective
    g_slot[p] = (int)key;

    float nx = __ldcs(normal + 3 * p + 0);
    float ny = __ldcs(normal + 3 * p + 1);
    float nz = __ldcs(normal + 3 * p + 2);
    float* fs = (float*)&g_sums[key];   // 16B-aligned slot: one sector
    atomicAdd(fs + 0, nx);
    atomicAdd(fs + 1, ny);
    atomicAdd(fs + 2, nz);
}

// ---------------------------------------------------------------------------
// Thread per point: diff = 1 - cos(normal, voxel_sum_n); global min/max.
__global__ void diff_kernel(const float* __restrict__ normal, int n) {
    __shared__ float sh_min[8];
    __shared__ float sh_max[8];

    float lmin = INFINITY;
    float lmax = -INFINITY;

    int stride = gridDim.x * blockDim.x;
    for (int p = blockIdx.x * blockDim.x + threadIdx.x; p < n; p += stride) {
        int s = g_slot[p];
        float d;
        if (s < 0) {
            d = -1.f;  // invalid marker
        } else {
            float4 f = g_sums[s];  // one 16B gather
            float nx = __ldcs(normal + 3 * p + 0);
            float ny = __ldcs(normal + 3 * p + 1);
            float nz = __ldcs(normal + 3 * p + 2);
            float sn = sqrtf(f.x * f.x + f.y * f.y + f.z * f.z);
            float nn = sqrtf(nx * nx + ny * ny + nz * nz);
            float inv = 1.f / (fmaxf(sn, 1e-6f) * fmaxf(nn, 1e-6f));
            float c = (f.x * nx + f.y * ny + f.z * nz) * inv;
            c = fminf(fmaxf(c, -1.f), 1.f);
            d = 1.f - c;
            lmin = fminf(lmin, d);
            lmax = fmaxf(lmax, d);
        }
        g_diff[p] = d;
    }

#pragma unroll
    for (int o = 16; o; o >>= 1) {
        lmin = fminf(lmin, __shfl_xor_sync(0xffffffffu, lmin, o));
        lmax = fmaxf(lmax, __shfl_xor_sync(0xffffffffu, lmax, o));
    }
    int wid = threadIdx.x >> 5, lane = threadIdx.x & 31;
    if (lane == 0) { sh_min[wid] = lmin; sh_max[wid] = lmax; }
    __syncthreads();
    if (wid == 0) {
        int nw = blockDim.x >> 5;
        lmin = (lane < nw) ? sh_min[lane] : INFINITY;
        lmax = (lane < nw) ? sh_max[lane] : -INFINITY;
#pragma unroll
        for (int o = 16; o; o >>= 1) {
            lmin = fminf(lmin, __shfl_xor_sync(0xffffffffu, lmin, o));
            lmax = fmaxf(lmax, __shfl_xor_sync(0xffffffffu, lmax, o));
        }
        if (lane == 0) {
            if (lmin <= 2.f) atomicMin(&g_dmin_bits, __float_as_uint(lmin));
            if (lmax >= 0.f) atomicMax(&g_dmax_bits, __float_as_uint(lmax));
        }
    }
}

// ---------------------------------------------------------------------------
// Warp per point: cross entropy (coalesced evict-first 128B row), weight, sum.
__global__ void finalize_kernel(const float* __restrict__ pred,
                                const void* __restrict__ target,
                                int n, int C) {
    __shared__ double sh_loss[8];
    __shared__ double sh_cnt[8];

    const bool is64 = (g_odd_or == 0u);
    float dmin = __uint_as_float(g_dmin_bits);
    float dmax = __uint_as_float(g_dmax_bits);
    float invr = 1.f / (dmax - dmin + 1e-6f);

    int lane = threadIdx.x & 31;
    int gw   = (blockIdx.x * blockDim.x + threadIdx.x) >> 5;
    int nwrp = (gridDim.x * blockDim.x) >> 5;

    double lsum = 0.0;
    double lcnt = 0.0;

    if (C == 32) {
        for (int p = gw; p < n; p += nwrp) {
            float d = g_diff[p];
            if (d < 0.f) continue;
            long long t = ld_idx_cs(target, p, is64);
            float x = __ldcs(pred + (size_t)p * 32u + lane);
            float m = x;
#pragma unroll
            for (int o = 16; o; o >>= 1) m = fmaxf(m, __shfl_xor_sync(0xffffffffu, m, o));
            float e = __expf(x - m);
#pragma unroll
            for (int o = 16; o; o >>= 1) e += __shfl_xor_sync(0xffffffffu, e, o);
            float xt = __shfl_sync(0xffffffffu, x, (int)t);
            if (lane == 0) {
                float ce = m + __logf(e) - xt;
                float dn = (d - dmin) * invr;
                dn = fminf(fmaxf(dn, 0.f), 1.f);
                lsum += (double)(ce * (1.f + 3.f * dn));
                lcnt += 1.0;
            }
        }
    } else {
        for (int p = gw; p < n; p += nwrp) {
            float d = g_diff[p];
            if (d < 0.f) continue;
            const float* row = pred + (size_t)p * (size_t)C;
            long long t = ld_idx_cs(target, p, is64);
            int iters = (C + 31) >> 5;
            if (iters > 8) iters = 8;  // C <= 256
            float xs[8];
            float m  = -INFINITY;
            float xt = 0.f;
#pragma unroll
            for (int i = 0; i < 8; i++) {
                if (i >= iters) break;
                int cidx = i * 32 + lane;
                float xv = (cidx < C) ? __ldcs(row + cidx) : -INFINITY;
                xs[i] = xv;
                m = fmaxf(m, xv);
                if ((long long)cidx == t) xt = xv;
            }
#pragma unroll
            for (int o = 16; o; o >>= 1) m = fmaxf(m, __shfl_xor_sync(0xffffffffu, m, o));
            float sum = 0.f;
#pragma unroll
            for (int i = 0; i < 8; i++) {
                if (i >= iters) break;
                sum += __expf(xs[i] - m);
            }
#pragma unroll
            for (int o = 16; o; o >>= 1) sum += __shfl_xor_sync(0xffffffffu, sum, o);
#pragma unroll
            for (int o = 16; o; o >>= 1) xt  += __shfl_xor_sync(0xffffffffu, xt, o);
            if (lane == 0) {
                float ce = m + __logf(sum) - xt;
                float dn = (d - dmin) * invr;
                dn = fminf(fmaxf(dn, 0.f), 1.f);
                lsum += (double)(ce * (1.f + 3.f * dn));
                lcnt += 1.0;
            }
        }
    }

    int wid = threadIdx.x >> 5;
    if (lane == 0) { sh_loss[wid] = lsum; sh_cnt[wid] = lcnt; }
    __syncthreads();
    if (wid == 0) {
        int nw = blockDim.x >> 5;
        lsum = (lane < nw) ? sh_loss[lane] : 0.0;
        lcnt = (lane < nw) ? sh_cnt[lane] : 0.0;
#pragma unroll
        for (int o = 16; o; o >>= 1) {
            lsum += __shfl_xor_sync(0xffffffffu, lsum, o);
            lcnt += __shfl_xor_sync(0xffffffffu, lcnt, o);
        }
        if (lane == 0) {
            atomicAdd(&g_loss, lsum);
            atomicAdd(&g_vm, lcnt);
        }
    }
}

// ---------------------------------------------------------------------------
__global__ void writeout_kernel(float* __restrict__ out) {
    double denom = g_vm > 1.0 ? g_vm : 1.0;
    out[0] = (float)(g_loss / denom);  // LOSS_WEIGHT = 1
}

// ---------------------------------------------------------------------------
// Streaming clear of the direct-indexed table (268MB of coalesced stores):
// restores zero state for the next graph replay.
__global__ void clear_kernel() {
    float4 z = make_float4(0.f, 0.f, 0.f, 0.f);
    unsigned int stride = gridDim.x * blockDim.x;
    for (unsigned int i = blockIdx.x * blockDim.x + threadIdx.x;
         i < (unsigned int)KEY_SPACE; i += stride)
        g_sums[i] = z;
}

// ---------------------------------------------------------------------------
extern "C" void kernel_launch(void* const* d_in, const int* in_sizes, int n_in,
                              void* d_out, int out_size) {
    const float* pred   = (const float*)d_in[0];
    const void*  target = d_in[1];
    const void*  gcoord = d_in[2];
    const float* normal = (const float*)d_in[3];
    const void*  batch  = d_in[4];
    float* out = (float*)d_out;

    int n = in_sizes[1];              // number of points
    int C = in_sizes[0] / n;          // number of classes (32)

    detect_init_kernel<<<128, 256>>>((const unsigned int*)gcoord, n * 3);

    {
        int threads = 256;
        int blocks = (n + threads - 1) / threads;
        scatter_kernel<<<blocks, threads>>>(gcoord, batch, target, normal, n);
    }

    {
        int threads = 256;
        int blocks = 2960;
        int need = (n + threads - 1) / threads;
        if (blocks > need) blocks = need;
        diff_kernel<<<blocks, threads>>>(normal, n);
    }

    finalize_kernel<<<2960, 256>>>(pred, target, n, C);

    writeout_kernel<<<1, 1>>>(out);

    clear_kernel<<<2960, 256>>>();
}

// round 8
// speedup vs baseline: 2.9070x; 2.2596x over previous
#include <cuda_runtime.h>
#include <math.h>
#include <stdint.h>

// ---------------------------------------------------------------------------
// NormalVariationBoundaryLoss
//   Voxel grouping by (x,y,z,batch) -> 24-bit key, direct-indexed table.
//   l2_normalize(sum/cnt) == l2_normalize(sum) -> only normal sums needed.
//   loss = sum(ce * w * vm) / max(sum vm, 1),
//   w = 1 + 3*clip((diff-dmin)/(dmax-dmin+1e-6),0,1),
//   diff = 1 - clip(cos(normalize(n), normalize(voxel_sum)), -1, 1)
//   CE: THREAD per point (8x float4 row load, register logsumexp, no shuffles)
// ---------------------------------------------------------------------------

#define KEY_SPACE (1 << 24)   // 16.7M slots
#define NMAX 2097152

// zero-initialized device scratch (allocation-free per harness rules)
__device__ float4       g_sums[KEY_SPACE];  // .x/.y/.z = normal sums (268MB)
__device__ int          g_slot[NMAX];       // 24-bit key or -1
__device__ float        g_diff[NMAX];
__device__ unsigned int g_dmin_bits;
__device__ unsigned int g_dmax_bits;
__device__ double       g_loss;
__device__ double       g_vm;
__device__ unsigned int g_odd_or;           // 0 => int inputs are int64

// ---------------------------------------------------------------------------
// Fused init + dtype detect (samples first 256K word-pairs: 1MB).
// int64 little-endian (values < 2^31) => all odd 32-bit words zero.
__global__ void detect_init_kernel(const unsigned int* __restrict__ w, int n32) {
    if (blockIdx.x == 0 && threadIdx.x == 0) {
        g_dmin_bits = 0x7f800000u;  // +inf
        g_dmax_bits = 0u;
        g_loss = 0.0;
        g_vm   = 0.0;
    }
    int limit = n32 / 2;
    if (limit > 262144) limit = 262144;
    unsigned int acc = 0u;
    int stride = gridDim.x * blockDim.x;
    for (int i = blockIdx.x * blockDim.x + threadIdx.x; i < limit; i += stride)
        acc |= __ldcs(w + 2 * i + 1);
#pragma unroll
    for (int o = 16; o; o >>= 1) acc |= __shfl_xor_sync(0xffffffffu, acc, o);
    if ((threadIdx.x & 31) == 0 && acc) atomicOr(&g_odd_or, acc);
}

__device__ __forceinline__ long long ld_idx_cs(const void* p, long long i, bool is64) {
    return is64 ? __ldcs((const long long*)p + i)
                : (long long)__ldcs((const int*)p + i);
}

// ---------------------------------------------------------------------------
// Per-point scatter: direct-indexed accumulation of normals. No CAS.
__global__ void scatter_kernel(const void* __restrict__ gc,
                               const void* __restrict__ batch,
                               const void* __restrict__ target,
                               const float* __restrict__ normal,
                               int n) {
    const bool is64 = (g_odd_or == 0u);
    int p = blockIdx.x * blockDim.x + threadIdx.x;
    if (p >= n) return;

    long long t = ld_idx_cs(target, p, is64);
    if (t == -1LL) { g_slot[p] = -1; return; }

    unsigned int x = (unsigned int)ld_idx_cs(gc, 3LL * p + 0, is64) & 127u;
    unsigned int y = (unsigned int)ld_idx_cs(gc, 3LL * p + 1, is64) & 127u;
    unsigned int z = (unsigned int)ld_idx_cs(gc, 3LL * p + 2, is64) & 127u;
    unsigned int b = (unsigned int)ld_idx_cs(batch, p, is64) & 7u;
    unsigned int key = (b << 21) | (x << 14) | (y << 7) | z;  // 24-bit, injective
    g_slot[p] = (int)key;

    float nx = __ldcs(normal + 3 * p + 0);
    float ny = __ldcs(normal + 3 * p + 1);
    float nz = __ldcs(normal + 3 * p + 2);
    float* fs = (float*)&g_sums[key];   // 16B-aligned slot: one sector
    atomicAdd(fs + 0, nx);
    atomicAdd(fs + 1, ny);
    atomicAdd(fs + 2, nz);
}

// ---------------------------------------------------------------------------
// Thread per point: diff = 1 - cos(normal, voxel_sum_n); global min/max.
__global__ void diff_kernel(const float* __restrict__ normal, int n) {
    __shared__ float sh_min[8];
    __shared__ float sh_max[8];

    float lmin = INFINITY;
    float lmax = -INFINITY;

    int stride = gridDim.x * blockDim.x;
    for (int p = blockIdx.x * blockDim.x + threadIdx.x; p < n; p += stride) {
        int s = g_slot[p];
        float d;
        if (s < 0) {
            d = -1.f;  // invalid marker
        } else {
            float4 f = g_sums[s];  // one 16B gather
            float nx = __ldcs(normal + 3 * p + 0);
            float ny = __ldcs(normal + 3 * p + 1);
            float nz = __ldcs(normal + 3 * p + 2);
            float sn = sqrtf(f.x * f.x + f.y * f.y + f.z * f.z);
            float nn = sqrtf(nx * nx + ny * ny + nz * nz);
            float inv = 1.f / (fmaxf(sn, 1e-6f) * fmaxf(nn, 1e-6f));
            float c = (f.x * nx + f.y * ny + f.z * nz) * inv;
            c = fminf(fmaxf(c, -1.f), 1.f);
            d = 1.f - c;
            lmin = fminf(lmin, d);
            lmax = fmaxf(lmax, d);
        }
        g_diff[p] = d;
    }

#pragma unroll
    for (int o = 16; o; o >>= 1) {
        lmin = fminf(lmin, __shfl_xor_sync(0xffffffffu, lmin, o));
        lmax = fmaxf(lmax, __shfl_xor_sync(0xffffffffu, lmax, o));
    }
    int wid = threadIdx.x >> 5, lane = threadIdx.x & 31;
    if (lane == 0) { sh_min[wid] = lmin; sh_max[wid] = lmax; }
    __syncthreads();
    if (wid == 0) {
        int nw = blockDim.x >> 5;
        lmin = (lane < nw) ? sh_min[lane] : INFINITY;
        lmax = (lane < nw) ? sh_max[lane] : -INFINITY;
#pragma unroll
        for (int o = 16; o; o >>= 1) {
            lmin = fminf(lmin, __shfl_xor_sync(0xffffffffu, lmin, o));
            lmax = fmaxf(lmax, __shfl_xor_sync(0xffffffffu, lmax, o));
        }
        if (lane == 0) {
            if (lmin <= 2.f) atomicMin(&g_dmin_bits, __float_as_uint(lmin));
            if (lmax >= 0.f) atomicMax(&g_dmax_bits, __float_as_uint(lmax));
        }
    }
}

// ---------------------------------------------------------------------------
// THREAD per point CE (C==32 fast path): 8 independent float4 loads, all
// logsumexp math in registers. No warp reductions anywhere on the hot path.
__global__ void finalize_kernel(const float* __restrict__ pred,
                                const void* __restrict__ target,
                                int n, int C) {
    __shared__ double sh_loss[8];
    __shared__ double sh_cnt[8];

    const bool is64 = (g_odd_or == 0u);
    float dmin = __uint_as_float(g_dmin_bits);
    float dmax = __uint_as_float(g_dmax_bits);
    float invr = 1.f / (dmax - dmin + 1e-6f);

    double lsum = 0.0;
    double lcnt = 0.0;

    int stride = gridDim.x * blockDim.x;

    if (C == 32) {
        for (int p = blockIdx.x * blockDim.x + threadIdx.x; p < n; p += stride) {
            float d = g_diff[p];
            if (d < 0.f) continue;
            int t = (int)ld_idx_cs(target, p, is64);

            const float4* row = (const float4*)(pred + (size_t)p * 32u);
            float4 v[8];
#pragma unroll
            for (int i = 0; i < 8; i++) v[i] = __ldcs(row + i);

            float xv[32];
#pragma unroll
            for (int i = 0; i < 8; i++) {
                xv[4 * i + 0] = v[i].x; xv[4 * i + 1] = v[i].y;
                xv[4 * i + 2] = v[i].z; xv[4 * i + 3] = v[i].w;
            }
            float m = xv[0];
#pragma unroll
            for (int i = 1; i < 32; i++) m = fmaxf(m, xv[i]);
            float e = 0.f;
#pragma unroll
            for (int i = 0; i < 32; i++) e += __expf(xv[i] - m);
            float xt = xv[t & 31];

            float ce = m + __logf(e) - xt;
            float dn = (d - dmin) * invr;
            dn = fminf(fmaxf(dn, 0.f), 1.f);
            lsum += (double)(ce * (1.f + 3.f * dn));
            lcnt += 1.0;
        }
    } else {
        // generic path: warp per point (rare; C != 32)
        int lane = threadIdx.x & 31;
        int gw   = (blockIdx.x * blockDim.x + threadIdx.x) >> 5;
        int nwrp = stride >> 5;
        for (int p = gw; p < n; p += nwrp) {
            float d = g_diff[p];
            if (d < 0.f) continue;
            const float* row = pred + (size_t)p * (size_t)C;
            long long t = ld_idx_cs(target, p, is64);
            int iters = (C + 31) >> 5;
            if (iters > 8) iters = 8;  // C <= 256
            float xs[8];
            float m  = -INFINITY;
            float xt = 0.f;
#pragma unroll
            for (int i = 0; i < 8; i++) {
                if (i >= iters) break;
                int cidx = i * 32 + lane;
                float xvv = (cidx < C) ? __ldcs(row + cidx) : -INFINITY;
                xs[i] = xvv;
                m = fmaxf(m, xvv);
                if ((long long)cidx == t) xt = xvv;
            }
#pragma unroll
            for (int o = 16; o; o >>= 1) m = fmaxf(m, __shfl_xor_sync(0xffffffffu, m, o));
            float sum = 0.f;
#pragma unroll
            for (int i = 0; i < 8; i++) {
                if (i >= iters) break;
                sum += __expf(xs[i] - m);
            }
#pragma unroll
            for (int o = 16; o; o >>= 1) sum += __shfl_xor_sync(0xffffffffu, sum, o);
#pragma unroll
            for (int o = 16; o; o >>= 1) xt  += __shfl_xor_sync(0xffffffffu, xt, o);
            if (lane == 0) {
                float ce = m + __logf(sum) - xt;
                float dn = (d - dmin) * invr;
                dn = fminf(fmaxf(dn, 0.f), 1.f);
                lsum += (double)(ce * (1.f + 3.f * dn));
                lcnt += 1.0;
            }
        }
    }

    // block reduction
#pragma unroll
    for (int o = 16; o; o >>= 1) {
        lsum += __shfl_xor_sync(0xffffffffu, lsum, o);
        lcnt += __shfl_xor_sync(0xffffffffu, lcnt, o);
    }
    int wid = threadIdx.x >> 5, lane = threadIdx.x & 31;
    if (lane == 0) { sh_loss[wid] = lsum; sh_cnt[wid] = lcnt; }
    __syncthreads();
    if (wid == 0) {
        int nw = blockDim.x >> 5;
        lsum = (lane < nw) ? sh_loss[lane] : 0.0;
        lcnt = (lane < nw) ? sh_cnt[lane] : 0.0;
#pragma unroll
        for (int o = 16; o; o >>= 1) {
            lsum += __shfl_xor_sync(0xffffffffu, lsum, o);
            lcnt += __shfl_xor_sync(0xffffffffu, lcnt, o);
        }
        if (lane == 0) {
            atomicAdd(&g_loss, lsum);
            atomicAdd(&g_vm, lcnt);
        }
    }
}

// ---------------------------------------------------------------------------
__global__ void writeout_kernel(float* __restrict__ out) {
    double denom = g_vm > 1.0 ? g_vm : 1.0;
    out[0] = (float)(g_loss / denom);  // LOSS_WEIGHT = 1
}

// ---------------------------------------------------------------------------
// Streaming clear of the direct-indexed table (268MB of coalesced stores):
// restores zero state for the next graph replay.
__global__ void clear_kernel() {
    float4 z = make_float4(0.f, 0.f, 0.f, 0.f);
    unsigned int stride = gridDim.x * blockDim.x;
    for (unsigned int i = blockIdx.x * blockDim.x + threadIdx.x;
         i < (unsigned int)KEY_SPACE; i += stride)
        g_sums[i] = z;
}

// ---------------------------------------------------------------------------
extern "C" void kernel_launch(void* const* d_in, const int* in_sizes, int n_in,
                              void* d_out, int out_size) {
    const float* pred   = (const float*)d_in[0];
    const void*  target = d_in[1];
    const void*  gcoord = d_in[2];
    const float* normal = (const float*)d_in[3];
    const void*  batch  = d_in[4];
    float* out = (float*)d_out;

    int n = in_sizes[1];              // number of points
    int C = in_sizes[0] / n;          // number of classes (32)

    detect_init_kernel<<<128, 256>>>((const unsigned int*)gcoord, n * 3);

    {
        int threads = 256;
        int blocks = (n + threads - 1) / threads;
        scatter_kernel<<<blocks, threads>>>(gcoord, batch, target, normal, n);
    }

    {
        int threads = 256;
        int blocks = 2960;
        int need = (n + threads - 1) / threads;
        if (blocks > need) blocks = need;
        diff_kernel<<<blocks, threads>>>(normal, n);
    }

    {
        int threads = 256;
        int blocks = (C == 32) ? (n + threads - 1) / threads : 2960;
        finalize_kernel<<<blocks, threads>>>(pred, target, n, C);
    }

    writeout_kernel<<<1, 1>>>(out);

    clear_kernel<<<2960, 256>>>();
}

// round 9
// speedup vs baseline: 3.3093x; 1.1384x over previous
#include <cuda_runtime.h>
#include <math.h>
#include <stdint.h>

// ---------------------------------------------------------------------------
// NormalVariationBoundaryLoss
//   Voxel grouping by (x,y,z,batch) -> 24-bit key, direct-indexed table.
//   l2_normalize(sum/cnt) == l2_normalize(sum) -> only normal sums needed.
//   loss = sum(ce * w * vm) / max(sum vm, 1)
//   CE (C==32): block stages 256 pred rows in smem via coalesced float4
//   loads (4 lines/LDG instead of 32), padded stride 33 for bank-free LDS.
//   Table clear fused into finalize tail (overlaps L1-bound CE with
//   DRAM-store-bound clear across blocks).
// ---------------------------------------------------------------------------

#define KEY_SPACE (1 << 24)   // 16.7M slots
#define NMAX 2097152

// zero-initialized device scratch (allocation-free per harness rules)
__device__ float4       g_sums[KEY_SPACE];  // .x/.y/.z = normal sums (268MB)
__device__ int          g_slot[NMAX];       // 24-bit key or -1
__device__ float        g_diff[NMAX];
__device__ unsigned int g_dmin_bits;
__device__ unsigned int g_dmax_bits;
__device__ double       g_loss;
__device__ double       g_vm;
__device__ unsigned int g_odd_or;           // 0 => int inputs are int64

// ---------------------------------------------------------------------------
__global__ void detect_init_kernel(const unsigned int* __restrict__ w, int n32) {
    if (blockIdx.x == 0 && threadIdx.x == 0) {
        g_dmin_bits = 0x7f800000u;  // +inf
        g_dmax_bits = 0u;
        g_loss = 0.0;
        g_vm   = 0.0;
    }
    int limit = n32 / 2;
    if (limit > 262144) limit = 262144;
    unsigned int acc = 0u;
    int stride = gridDim.x * blockDim.x;
    for (int i = blockIdx.x * blockDim.x + threadIdx.x; i < limit; i += stride)
        acc |= __ldcs(w + 2 * i + 1);
#pragma unroll
    for (int o = 16; o; o >>= 1) acc |= __shfl_xor_sync(0xffffffffu, acc, o);
    if ((threadIdx.x & 31) == 0 && acc) atomicOr(&g_odd_or, acc);
}

__device__ __forceinline__ long long ld_idx_cs(const void* p, long long i, bool is64) {
    return is64 ? __ldcs((const long long*)p + i)
                : (long long)__ldcs((const int*)p + i);
}

// ---------------------------------------------------------------------------
// Per-point scatter: direct-indexed accumulation of normals.
__global__ void scatter_kernel(const void* __restrict__ gc,
                               const void* __restrict__ batch,
                               const void* __restrict__ target,
                               const float* __restrict__ normal,
                               int n) {
    const bool is64 = (g_odd_or == 0u);
    int p = blockIdx.x * blockDim.x + threadIdx.x;
    if (p >= n) return;

    long long t = ld_idx_cs(target, p, is64);
    if (t == -1LL) { g_slot[p] = -1; return; }

    unsigned int x = (unsigned int)ld_idx_cs(gc, 3LL * p + 0, is64) & 127u;
    unsigned int y = (unsigned int)ld_idx_cs(gc, 3LL * p + 1, is64) & 127u;
    unsigned int z = (unsigned int)ld_idx_cs(gc, 3LL * p + 2, is64) & 127u;
    unsigned int b = (unsigned int)ld_idx_cs(batch, p, is64) & 7u;
    unsigned int key = (b << 21) | (x << 14) | (y << 7) | z;  // injective
    g_slot[p] = (int)key;

    float nx = __ldcs(normal + 3 * p + 0);
    float ny = __ldcs(normal + 3 * p + 1);
    float nz = __ldcs(normal + 3 * p + 2);
    float* fs = (float*)&g_sums[key];
    atomicAdd(fs + 0, nx);
    atomicAdd(fs + 1, ny);
    atomicAdd(fs + 2, nz);
}

// ---------------------------------------------------------------------------
// Thread per point: diff = 1 - cos(normal, voxel_sum_n); global min/max.
__global__ void diff_kernel(const float* __restrict__ normal, int n) {
    __shared__ float sh_min[8];
    __shared__ float sh_max[8];

    float lmin = INFINITY;
    float lmax = -INFINITY;

    int stride = gridDim.x * blockDim.x;
    for (int p = blockIdx.x * blockDim.x + threadIdx.x; p < n; p += stride) {
        int s = g_slot[p];
        float d;
        if (s < 0) {
            d = -1.f;
        } else {
            float4 f = g_sums[s];
            float nx = __ldcs(normal + 3 * p + 0);
            float ny = __ldcs(normal + 3 * p + 1);
            float nz = __ldcs(normal + 3 * p + 2);
            float sn = sqrtf(f.x * f.x + f.y * f.y + f.z * f.z);
            float nn = sqrtf(nx * nx + ny * ny + nz * nz);
            float inv = 1.f / (fmaxf(sn, 1e-6f) * fmaxf(nn, 1e-6f));
            float c = (f.x * nx + f.y * ny + f.z * nz) * inv;
            c = fminf(fmaxf(c, -1.f), 1.f);
            d = 1.f - c;
            lmin = fminf(lmin, d);
            lmax = fmaxf(lmax, d);
        }
        g_diff[p] = d;
    }

#pragma unroll
    for (int o = 16; o; o >>= 1) {
        lmin = fminf(lmin, __shfl_xor_sync(0xffffffffu, lmin, o));
        lmax = fmaxf(lmax, __shfl_xor_sync(0xffffffffu, lmax, o));
    }
    int wid = threadIdx.x >> 5, lane = threadIdx.x & 31;
    if (lane == 0) { sh_min[wid] = lmin; sh_max[wid] = lmax; }
    __syncthreads();
    if (wid == 0) {
        int nw = blockDim.x >> 5;
        lmin = (lane < nw) ? sh_min[lane] : INFINITY;
        lmax = (lane < nw) ? sh_max[lane] : -INFINITY;
#pragma unroll
        for (int o = 16; o; o >>= 1) {
            lmin = fminf(lmin, __shfl_xor_sync(0xffffffffu, lmin, o));
            lmax = fmaxf(lmax, __shfl_xor_sync(0xffffffffu, lmax, o));
        }
        if (lane == 0) {
            if (lmin <= 2.f) atomicMin(&g_dmin_bits, __float_as_uint(lmin));
            if (lmax >= 0.f) atomicMax(&g_dmax_bits, __float_as_uint(lmax));
        }
    }
}

// ---------------------------------------------------------------------------
// C==32 fused finalize: smem-staged coalesced pred tile + CE + loss reduce,
// then a grid-stride streaming clear of g_sums.
#define TPB 256
#define ROWPAD 33   // 33-float row stride: bank = (pt + j) % 32 -> conflict-free

__global__ void finalize32_kernel(const float* __restrict__ pred,
                                  const void* __restrict__ target,
                                  int n) {
    __shared__ float  tile[TPB * ROWPAD];     // 33KB
    __shared__ double sh_loss[8];
    __shared__ double sh_cnt[8];

    const bool is64 = (g_odd_or == 0u);
    float dmin = __uint_as_float(g_dmin_bits);
    float dmax = __uint_as_float(g_dmax_bits);
    float invr = 1.f / (dmax - dmin + 1e-6f);

    int t = threadIdx.x;
    int base = blockIdx.x * TPB;              // first point of this tile

    // ---- stage tile: coalesced float4 loads (512B per warp-instruction) ----
    const float4* pred4 = (const float4*)pred;
    long long base4 = (long long)base * 8;    // 8 float4 per 32-float row
    long long n4    = (long long)n * 8;
#pragma unroll
    for (int k = 0; k < 8; k++) {
        long long idx = base4 + t + k * TPB;
        if (idx < n4) {
            float4 f = __ldcs(pred4 + idx);
            int loc = t + k * TPB;            // 0..2047
            int pt  = loc >> 3;               // local point
            int q   = loc & 7;                // quarter-row
            float* dst = &tile[pt * ROWPAD + q * 4];
            dst[0] = f.x; dst[1] = f.y; dst[2] = f.z; dst[3] = f.w;
        }
    }
    __syncthreads();

    // ---- per-thread CE from smem ----
    double lsum = 0.0;
    double lcnt = 0.0;
    int p = base + t;
    if (p < n) {
        float d = g_diff[p];
        if (d >= 0.f) {
            int tg = (int)ld_idx_cs(target, p, is64) & 31;
            const float* row = &tile[t * ROWPAD];
            float m = row[0];
#pragma unroll
            for (int j = 1; j < 32; j++) m = fmaxf(m, row[j]);
            float e = 0.f;
#pragma unroll
            for (int j = 0; j < 32; j++) e += __expf(row[j] - m);
            float xt = row[tg];
            float ce = m + __logf(e) - xt;
            float dn = (d - dmin) * invr;
            dn = fminf(fmaxf(dn, 0.f), 1.f);
            lsum = (double)(ce * (1.f + 3.f * dn));
            lcnt = 1.0;
        }
    }

    // ---- block reduce + atomics ----
#pragma unroll
    for (int o = 16; o; o >>= 1) {
        lsum += __shfl_xor_sync(0xffffffffu, lsum, o);
        lcnt += __shfl_xor_sync(0xffffffffu, lcnt, o);
    }
    int wid = t >> 5, lane = t & 31;
    if (lane == 0) { sh_loss[wid] = lsum; sh_cnt[wid] = lcnt; }
    __syncthreads();
    if (wid == 0) {
        int nw = TPB >> 5;
        lsum = (lane < nw) ? sh_loss[lane] : 0.0;
        lcnt = (lane < nw) ? sh_cnt[lane] : 0.0;
#pragma unroll
        for (int o = 16; o; o >>= 1) {
            lsum += __shfl_xor_sync(0xffffffffu, lsum, o);
            lcnt += __shfl_xor_sync(0xffffffffu, lcnt, o);
        }
        if (lane == 0) {
            atomicAdd(&g_loss, lsum);
            atomicAdd(&g_vm, lcnt);
        }
    }

    // ---- fused streaming clear of g_sums (overlaps across blocks) ----
    float4 z = make_float4(0.f, 0.f, 0.f, 0.f);
    unsigned int cstride = gridDim.x * blockDim.x;
    for (unsigned int i = blockIdx.x * blockDim.x + threadIdx.x;
         i < (unsigned int)KEY_SPACE; i += cstride)
        g_sums[i] = z;
}

// ---------------------------------------------------------------------------
// Generic-C finalize (warp per point) — fallback only.
__global__ void finalize_generic_kernel(const float* __restrict__ pred,
                                        const void* __restrict__ target,
                                        int n, int C) {
    __shared__ double sh_loss[8];
    __shared__ double sh_cnt[8];

    const bool is64 = (g_odd_or == 0u);
    float dmin = __uint_as_float(g_dmin_bits);
    float dmax = __uint_as_float(g_dmax_bits);
    float invr = 1.f / (dmax - dmin + 1e-6f);

    int lane = threadIdx.x & 31;
    int gw   = (blockIdx.x * blockDim.x + threadIdx.x) >> 5;
    int nwrp = (gridDim.x * blockDim.x) >> 5;

    double lsum = 0.0;
    double lcnt = 0.0;

    for (int p = gw; p < n; p += nwrp) {
        float d = g_diff[p];
        if (d < 0.f) continue;
        const float* row = pred + (size_t)p * (size_t)C;
        long long t = ld_idx_cs(target, p, is64);
        int iters = (C + 31) >> 5;
        if (iters > 8) iters = 8;  // C <= 256
        float xs[8];
        float m  = -INFINITY;
        float xt = 0.f;
#pragma unroll
        for (int i = 0; i < 8; i++) {
            if (i >= iters) break;
            int cidx = i * 32 + lane;
            float xv = (cidx < C) ? __ldcs(row + cidx) : -INFINITY;
            xs[i] = xv;
            m = fmaxf(m, xv);
            if ((long long)cidx == t) xt = xv;
        }
#pragma unroll
        for (int o = 16; o; o >>= 1) m = fmaxf(m, __shfl_xor_sync(0xffffffffu, m, o));
        float sum = 0.f;
#pragma unroll
        for (int i = 0; i < 8; i++) {
            if (i >= iters) break;
            sum += __expf(xs[i] - m);
        }
#pragma unroll
        for (int o = 16; o; o >>= 1) sum += __shfl_xor_sync(0xffffffffu, sum, o);
#pragma unroll
        for (int o = 16; o; o >>= 1) xt  += __shfl_xor_sync(0xffffffffu, xt, o);
        if (lane == 0) {
            float ce = m + __logf(sum) - xt;
            float dn = (d - dmin) * invr;
            dn = fminf(fmaxf(dn, 0.f), 1.f);
            lsum += (double)(ce * (1.f + 3.f * dn));
            lcnt += 1.0;
        }
    }

#pragma unroll
    for (int o = 16; o; o >>= 1) {
        lsum += __shfl_xor_sync(0xffffffffu, lsum, o);
        lcnt += __shfl_xor_sync(0xffffffffu, lcnt, o);
    }
    int wid = threadIdx.x >> 5;
    if (lane == 0) { sh_loss[wid] = lsum; sh_cnt[wid] = lcnt; }
    __syncthreads();
    if (wid == 0) {
        int nw = blockDim.x >> 5;
        lsum = (lane < nw) ? sh_loss[lane] : 0.0;
        lcnt = (lane < nw) ? sh_cnt[lane] : 0.0;
#pragma unroll
        for (int o = 16; o; o >>= 1) {
            lsum += __shfl_xor_sync(0xffffffffu, lsum, o);
            lcnt += __shfl_xor_sync(0xffffffffu, lcnt, o);
        }
        if (lane == 0) {
            atomicAdd(&g_loss, lsum);
            atomicAdd(&g_vm, lcnt);
        }
    }
}

// ---------------------------------------------------------------------------
__global__ void clear_kernel() {
    float4 z = make_float4(0.f, 0.f, 0.f, 0.f);
    unsigned int stride = gridDim.x * blockDim.x;
    for (unsigned int i = blockIdx.x * blockDim.x + threadIdx.x;
         i < (unsigned int)KEY_SPACE; i += stride)
        g_sums[i] = z;
}

// ---------------------------------------------------------------------------
__global__ void writeout_kernel(float* __restrict__ out) {
    double denom = g_vm > 1.0 ? g_vm : 1.0;
    out[0] = (float)(g_loss / denom);  // LOSS_WEIGHT = 1
}

// ---------------------------------------------------------------------------
extern "C" void kernel_launch(void* const* d_in, const int* in_sizes, int n_in,
                              void* d_out, int out_size) {
    const float* pred   = (const float*)d_in[0];
    const void*  target = d_in[1];
    const void*  gcoord = d_in[2];
    const float* normal = (const float*)d_in[3];
    const void*  batch  = d_in[4];
    float* out = (float*)d_out;

    int n = in_sizes[1];              // number of points
    int C = in_sizes[0] / n;          // number of classes (32)

    detect_init_kernel<<<128, 256>>>((const unsigned int*)gcoord, n * 3);

    {
        int threads = 256;
        int blocks = (n + threads - 1) / threads;
        scatter_kernel<<<blocks, threads>>>(gcoord, batch, target, normal, n);
    }

    {
        int threads = 256;
        int blocks = 2960;
        int need = (n + threads - 1) / threads;
        if (blocks > need) blocks = need;
        diff_kernel<<<blocks, threads>>>(normal, n);
    }

    if (C == 32) {
        int blocks = (n + TPB - 1) / TPB;
        finalize32_kernel<<<blocks, TPB>>>(pred, target, n);   // clear fused
    } else {
        finalize_generic_kernel<<<2960, 256>>>(pred, target, n, C);
        clear_kernel<<<2960, 256>>>();
    }

    writeout_kernel<<<1, 1>>>(out);
}

// round 10
// speedup vs baseline: 3.5407x; 1.0699x over previous
#include <cuda_runtime.h>
#include <math.h>
#include <stdint.h>

// ---------------------------------------------------------------------------
// NormalVariationBoundaryLoss
//   Voxel grouping by (x,y,z,batch) -> 24-bit key, direct-indexed table.
//   l2_normalize(sum/cnt) == l2_normalize(sum) -> only normal sums needed.
//   Scatter: ONE red.global.add.v4.f32 per point (16B vector atomic).
//   Clear: scattered per-dirty-slot 16B stores in finalize (64MB vs 268MB).
// ---------------------------------------------------------------------------

#define KEY_SPACE (1 << 24)   // 16.7M slots
#define NMAX 2097152

// zero-initialized device scratch (allocation-free per harness rules)
__device__ float4       g_sums[KEY_SPACE];  // .x/.y/.z = normal sums (268MB)
__device__ int          g_slot[NMAX];       // 24-bit key or -1
__device__ float        g_diff[NMAX];
__device__ unsigned int g_dmin_bits;
__device__ unsigned int g_dmax_bits;
__device__ double       g_loss;
__device__ double       g_vm;
__device__ unsigned int g_odd_or;           // 0 => int inputs are int64

// ---------------------------------------------------------------------------
__global__ void detect_init_kernel(const unsigned int* __restrict__ w, int n32) {
    if (blockIdx.x == 0 && threadIdx.x == 0) {
        g_dmin_bits = 0x7f800000u;  // +inf
        g_dmax_bits = 0u;
        g_loss = 0.0;
        g_vm   = 0.0;
    }
    int limit = n32 / 2;
    if (limit > 262144) limit = 262144;
    unsigned int acc = 0u;
    int stride = gridDim.x * blockDim.x;
    for (int i = blockIdx.x * blockDim.x + threadIdx.x; i < limit; i += stride)
        acc |= __ldcs(w + 2 * i + 1);
#pragma unroll
    for (int o = 16; o; o >>= 1) acc |= __shfl_xor_sync(0xffffffffu, acc, o);
    if ((threadIdx.x & 31) == 0 && acc) atomicOr(&g_odd_or, acc);
}

__device__ __forceinline__ long long ld_idx_cs(const void* p, long long i, bool is64) {
    return is64 ? __ldcs((const long long*)p + i)
                : (long long)__ldcs((const int*)p + i);
}

// vector reduction: one 16B atomic add (sm_90+)
__device__ __forceinline__ void red_add_v4(float4* a, float x, float y, float z) {
    unsigned long long ga = __cvta_generic_to_global(a);
    asm volatile("red.global.add.v4.f32 [%0], {%1, %2, %3, %4};"
                 :: "l"(ga), "f"(x), "f"(y), "f"(z), "f"(0.f) : "memory");
}

// ---------------------------------------------------------------------------
// Per-point scatter: direct-indexed accumulation of normals (1 atomic/point).
__global__ void scatter_kernel(const void* __restrict__ gc,
                               const void* __restrict__ batch,
                               const void* __restrict__ target,
                               const float* __restrict__ normal,
                               int n) {
    const bool is64 = (g_odd_or == 0u);
    int p = blockIdx.x * blockDim.x + threadIdx.x;
    if (p >= n) return;

    long long t = ld_idx_cs(target, p, is64);
    if (t == -1LL) { g_slot[p] = -1; return; }

    unsigned int x = (unsigned int)ld_idx_cs(gc, 3LL * p + 0, is64) & 127u;
    unsigned int y = (unsigned int)ld_idx_cs(gc, 3LL * p + 1, is64) & 127u;
    unsigned int z = (unsigned int)ld_idx_cs(gc, 3LL * p + 2, is64) & 127u;
    unsigned int b = (unsigned int)ld_idx_cs(batch, p, is64) & 7u;
    unsigned int key = (b << 21) | (x << 14) | (y << 7) | z;  // injective
    g_slot[p] = (int)key;

    float nx = __ldcs(normal + 3 * p + 0);
    float ny = __ldcs(normal + 3 * p + 1);
    float nz = __ldcs(normal + 3 * p + 2);
    red_add_v4(&g_sums[key], nx, ny, nz);
}

// ---------------------------------------------------------------------------
// Thread per point: diff = 1 - cos(normal, voxel_sum_n); global min/max.
__global__ void diff_kernel(const float* __restrict__ normal, int n) {
    __shared__ float sh_min[8];
    __shared__ float sh_max[8];

    float lmin = INFINITY;
    float lmax = -INFINITY;

    int stride = gridDim.x * blockDim.x;
    for (int p = blockIdx.x * blockDim.x + threadIdx.x; p < n; p += stride) {
        int s = g_slot[p];
        float d;
        if (s < 0) {
            d = -1.f;
        } else {
            float4 f = g_sums[s];
            float nx = __ldcs(normal + 3 * p + 0);
            float ny = __ldcs(normal + 3 * p + 1);
            float nz = __ldcs(normal + 3 * p + 2);
            float sn = sqrtf(f.x * f.x + f.y * f.y + f.z * f.z);
            float nn = sqrtf(nx * nx + ny * ny + nz * nz);
            float inv = 1.f / (fmaxf(sn, 1e-6f) * fmaxf(nn, 1e-6f));
            float c = (f.x * nx + f.y * ny + f.z * nz) * inv;
            c = fminf(fmaxf(c, -1.f), 1.f);
            d = 1.f - c;
            lmin = fminf(lmin, d);
            lmax = fmaxf(lmax, d);
        }
        g_diff[p] = d;
    }

#pragma unroll
    for (int o = 16; o; o >>= 1) {
        lmin = fminf(lmin, __shfl_xor_sync(0xffffffffu, lmin, o));
        lmax = fmaxf(lmax, __shfl_xor_sync(0xffffffffu, lmax, o));
    }
    int wid = threadIdx.x >> 5, lane = threadIdx.x & 31;
    if (lane == 0) { sh_min[wid] = lmin; sh_max[wid] = lmax; }
    __syncthreads();
    if (wid == 0) {
        int nw = blockDim.x >> 5;
        lmin = (lane < nw) ? sh_min[lane] : INFINITY;
        lmax = (lane < nw) ? sh_max[lane] : -INFINITY;
#pragma unroll
        for (int o = 16; o; o >>= 1) {
            lmin = fminf(lmin, __shfl_xor_sync(0xffffffffu, lmin, o));
            lmax = fmaxf(lmax, __shfl_xor_sync(0xffffffffu, lmax, o));
        }
        if (lane == 0) {
            if (lmin <= 2.f) atomicMin(&g_dmin_bits, __float_as_uint(lmin));
            if (lmax >= 0.f) atomicMax(&g_dmax_bits, __float_as_uint(lmax));
        }
    }
}

// ---------------------------------------------------------------------------
// C==32 fused finalize: smem-staged coalesced pred tile + CE + loss reduce +
// SCATTERED clear of exactly the dirty slots (via g_slot).
#define TPB 256
#define ROWPAD 33   // conflict-free smem row stride

__global__ void finalize32_kernel(const float* __restrict__ pred,
                                  const void* __restrict__ target,
                                  int n) {
    __shared__ float  tile[TPB * ROWPAD];     // 33KB
    __shared__ double sh_loss[8];
    __shared__ double sh_cnt[8];

    const bool is64 = (g_odd_or == 0u);
    float dmin = __uint_as_float(g_dmin_bits);
    float dmax = __uint_as_float(g_dmax_bits);
    float invr = 1.f / (dmax - dmin + 1e-6f);

    int t = threadIdx.x;
    int base = blockIdx.x * TPB;              // first point of this tile

    // ---- stage tile: coalesced float4 loads ----
    const float4* pred4 = (const float4*)pred;
    long long base4 = (long long)base * 8;
    long long n4    = (long long)n * 8;
#pragma unroll
    for (int k = 0; k < 8; k++) {
        long long idx = base4 + t + k * TPB;
        if (idx < n4) {
            float4 f = __ldcs(pred4 + idx);
            int loc = t + k * TPB;
            int pt  = loc >> 3;
            int q   = loc & 7;
            float* dst = &tile[pt * ROWPAD + q * 4];
            dst[0] = f.x; dst[1] = f.y; dst[2] = f.z; dst[3] = f.w;
        }
    }
    __syncthreads();

    // ---- per-thread CE from smem + scattered slot clear ----
    double lsum = 0.0;
    double lcnt = 0.0;
    int p = base + t;
    if (p < n) {
        int s = g_slot[p];
        if (s >= 0) {
            // clear this point's slot (duplicates benign; diff pass is done)
            g_sums[s] = make_float4(0.f, 0.f, 0.f, 0.f);

            float d = g_diff[p];
            int tg = (int)ld_idx_cs(target, p, is64) & 31;
            const float* row = &tile[t * ROWPAD];
            float m = row[0];
#pragma unroll
            for (int j = 1; j < 32; j++) m = fmaxf(m, row[j]);
            float e = 0.f;
#pragma unroll
            for (int j = 0; j < 32; j++) e += __expf(row[j] - m);
            float xt = row[tg];
            float ce = m + __logf(e) - xt;
            float dn = (d - dmin) * invr;
            dn = fminf(fmaxf(dn, 0.f), 1.f);
            lsum = (double)(ce * (1.f + 3.f * dn));
            lcnt = 1.0;
        }
    }

    // ---- block reduce + atomics ----
#pragma unroll
    for (int o = 16; o; o >>= 1) {
        lsum += __shfl_xor_sync(0xffffffffu, lsum, o);
        lcnt += __shfl_xor_sync(0xffffffffu, lcnt, o);
    }
    int wid = t >> 5, lane = t & 31;
    if (lane == 0) { sh_loss[wid] = lsum; sh_cnt[wid] = lcnt; }
    __syncthreads();
    if (wid == 0) {
        int nw = TPB >> 5;
        lsum = (lane < nw) ? sh_loss[lane] : 0.0;
        lcnt = (lane < nw) ? sh_cnt[lane] : 0.0;
#pragma unroll
        for (int o = 16; o; o >>= 1) {
            lsum += __shfl_xor_sync(0xffffffffu, lsum, o);
            lcnt += __shfl_xor_sync(0xffffffffu, lcnt, o);
        }
        if (lane == 0) {
            atomicAdd(&g_loss, lsum);
            atomicAdd(&g_vm, lcnt);
        }
    }
}

// ---------------------------------------------------------------------------
// Generic-C finalize (warp per point) + scattered clear — fallback only.
__global__ void finalize_generic_kernel(const float* __restrict__ pred,
                                        const void* __restrict__ target,
                                        int n, int C) {
    __shared__ double sh_loss[8];
    __shared__ double sh_cnt[8];

    const bool is64 = (g_odd_or == 0u);
    float dmin = __uint_as_float(g_dmin_bits);
    float dmax = __uint_as_float(g_dmax_bits);
    float invr = 1.f / (dmax - dmin + 1e-6f);

    int lane = threadIdx.x & 31;
    int gw   = (blockIdx.x * blockDim.x + threadIdx.x) >> 5;
    int nwrp = (gridDim.x * blockDim.x) >> 5;

    double lsum = 0.0;
    double lcnt = 0.0;

    for (int p = gw; p < n; p += nwrp) {
        float d = g_diff[p];
        if (d < 0.f) continue;
        if (lane == 0) {
            int s = g_slot[p];
            if (s >= 0) g_sums[s] = make_float4(0.f, 0.f, 0.f, 0.f);
        }
        const float* row = pred + (size_t)p * (size_t)C;
        long long t = ld_idx_cs(target, p, is64);
        int iters = (C + 31) >> 5;
        if (iters > 8) iters = 8;  // C <= 256
        float xs[8];
        float m  = -INFINITY;
        float xt = 0.f;
#pragma unroll
        for (int i = 0; i < 8; i++) {
            if (i >= iters) break;
            int cidx = i * 32 + lane;
            float xv = (cidx < C) ? __ldcs(row + cidx) : -INFINITY;
            xs[i] = xv;
            m = fmaxf(m, xv);
            if ((long long)cidx == t) xt = xv;
        }
#pragma unroll
        for (int o = 16; o; o >>= 1) m = fmaxf(m, __shfl_xor_sync(0xffffffffu, m, o));
        float sum = 0.f;
#pragma unroll
        for (int i = 0; i < 8; i++) {
            if (i >= iters) break;
            sum += __expf(xs[i] - m);
        }
#pragma unroll
        for (int o = 16; o; o >>= 1) sum += __shfl_xor_sync(0xffffffffu, sum, o);
#pragma unroll
        for (int o = 16; o; o >>= 1) xt  += __shfl_xor_sync(0xffffffffu, xt, o);
        if (lane == 0) {
            float ce = m + __logf(sum) - xt;
            float dn = (d - dmin) * invr;
            dn = fminf(fmaxf(dn, 0.f), 1.f);
            lsum += (double)(ce * (1.f + 3.f * dn));
            lcnt += 1.0;
        }
    }

#pragma unroll
    for (int o = 16; o; o >>= 1) {
        lsum += __shfl_xor_sync(0xffffffffu, lsum, o);
        lcnt += __shfl_xor_sync(0xffffffffu, lcnt, o);
    }
    int wid = threadIdx.x >> 5;
    if (lane == 0) { sh_loss[wid] = lsum; sh_cnt[wid] = lcnt; }
    __syncthreads();
    if (wid == 0) {
        int nw = blockDim.x >> 5;
        lsum = (lane < nw) ? sh_loss[lane] : 0.0;
        lcnt = (lane < nw) ? sh_cnt[lane] : 0.0;
#pragma unroll
        for (int o = 16; o; o >>= 1) {
            lsum += __shfl_xor_sync(0xffffffffu, lsum, o);
            lcnt += __shfl_xor_sync(0xffffffffu, lcnt, o);
        }
        if (lane == 0) {
            atomicAdd(&g_loss, lsum);
            atomicAdd(&g_vm, lcnt);
        }
    }
}

// ---------------------------------------------------------------------------
__global__ void writeout_kernel(float* __restrict__ out) {
    double denom = g_vm > 1.0 ? g_vm : 1.0;
    out[0] = (float)(g_loss / denom);  // LOSS_WEIGHT = 1
}

// ---------------------------------------------------------------------------
extern "C" void kernel_launch(void* const* d_in, const int* in_sizes, int n_in,
                              void* d_out, int out_size) {
    const float* pred   = (const float*)d_in[0];
    const void*  target = d_in[1];
    const void*  gcoord = d_in[2];
    const float* normal = (const float*)d_in[3];
    const void*  batch  = d_in[4];
    float* out = (float*)d_out;

    int n = in_sizes[1];              // number of points
    int C = in_sizes[0] / n;          // number of classes (32)

    detect_init_kernel<<<128, 256>>>((const unsigned int*)gcoord, n * 3);

    {
        int threads = 256;
        int blocks = (n + threads - 1) / threads;
        scatter_kernel<<<blocks, threads>>>(gcoord, batch, target, normal, n);
    }

    {
        int threads = 256;
        int blocks = 2960;
        int need = (n + threads - 1) / threads;
        if (blocks > need) blocks = need;
        diff_kernel<<<blocks, threads>>>(normal, n);
    }

    if (C == 32) {
        int blocks = (n + TPB - 1) / TPB;
        finalize32_kernel<<<blocks, TPB>>>(pred, target, n);   // scattered clear fused
    } else {
        finalize_generic_kernel<<<2960, 256>>>(pred, target, n, C);
    }

    writeout_kernel<<<1, 1>>>(out);
}